// round 2
// baseline (speedup 1.0000x reference)
#include <cuda_runtime.h>
#include <cuda_bf16.h>
#include <math.h>

#define BATCH 512
#define EPS 1e-5f

typedef unsigned long long ull;

// packed f32x2 FMA: d.lo = a.lo*b.lo + c.lo ; d.hi = a.hi*b.hi + c.hi
__device__ __forceinline__ ull ffma2(ull a, ull b, ull c) {
    ull d;
    asm("fma.rn.f32x2 %0, %1, %2, %3;" : "=l"(d) : "l"(a), "l"(b), "l"(c));
    return d;
}

union F2U { ull u; float2 f; };

// ---------------- scratch (no allocations allowed) ----------------
__device__ float g_out1[BATCH * 256 * 24 * 24];
__device__ float g_out2[BATCH * 128 * 12 * 12];
__device__ float g_out3[BATCH * 64 * 6 * 6];
__device__ float g_fc1[BATCH * 512];
__device__ float g_fc2[BATCH * 256];
__device__ float g_q[BATCH * 64];

// ---------------- block1: conv(1->256,48x48) + BN + ReLU + pool -> [B,256,24,24] ----------------
#define OCB1 32
__global__ void block1_kernel(const float* __restrict__ x, const float* __restrict__ w,
                              const float* __restrict__ cb, const float* __restrict__ gg,
                              const float* __restrict__ bb, const float* __restrict__ mm,
                              const float* __restrict__ vv, float* __restrict__ out) {
    int b = blockIdx.y;
    int oc0 = blockIdx.x * OCB1;
    __shared__ float tile[50 * 50];
    __shared__ float ws[OCB1 * 9];
    __shared__ float sa[OCB1], sc[OCB1];
    int tid = threadIdx.x;

    const float* xb = x + (size_t)b * 48 * 48;
    for (int i = tid; i < 2500; i += blockDim.x) {
        int r = i / 50, c = i % 50;
        float val = 0.f;
        if (r >= 1 && r <= 48 && c >= 1 && c <= 48) val = xb[(r - 1) * 48 + (c - 1)];
        tile[i] = val;
    }
    for (int i = tid; i < OCB1 * 9; i += blockDim.x) ws[i] = w[oc0 * 9 + i];
    if (tid < OCB1) {
        int oc = oc0 + tid;
        float inv = gg[oc] * rsqrtf(vv[oc] + EPS);
        sa[tid] = inv;
        sc[tid] = (cb[oc] - mm[oc]) * inv + bb[oc];
    }
    __syncthreads();

    for (int it = tid; it < 576; it += blockDim.x) {
        int ph = it / 24, pw = it % 24;
        float p[4][4];
#pragma unroll
        for (int i = 0; i < 4; i++)
#pragma unroll
            for (int j = 0; j < 4; j++)
                p[i][j] = tile[(2 * ph + i) * 50 + (2 * pw + j)];
#pragma unroll 4
        for (int oo = 0; oo < OCB1; oo++) {
            float a = sa[oo], cc = sc[oo];
            const float* wk = &ws[oo * 9];
            float w0 = wk[0], w1 = wk[1], w2 = wk[2], w3 = wk[3], w4 = wk[4],
                  w5 = wk[5], w6 = wk[6], w7 = wk[7], w8 = wk[8];
            float mx = -INFINITY;
#pragma unroll
            for (int py = 0; py < 2; py++)
#pragma unroll
                for (int px = 0; px < 2; px++) {
                    float s = p[py + 0][px + 0] * w0 + p[py + 0][px + 1] * w1 + p[py + 0][px + 2] * w2
                            + p[py + 1][px + 0] * w3 + p[py + 1][px + 1] * w4 + p[py + 1][px + 2] * w5
                            + p[py + 2][px + 0] * w6 + p[py + 2][px + 1] * w7 + p[py + 2][px + 2] * w8;
                    float y = fmaxf(fmaf(s, a, cc), 0.f);
                    mx = fmaxf(mx, y);
                }
            out[(((size_t)b * 256 + oc0 + oo) * 24 + ph) * 24 + pw] = mx;
        }
    }
}

// ---------------- packed-f32x2 fused conv(3x3,pad1)+BN+ReLU+pool block ----------------
// Each thread computes ONE output-channel PAIR over a (2*PT)x(2*PT) pre-pool patch.
// Patch values are broadcast pairs (duplicated smem tile, LDS.64).
// Weights are true pairs (interleaved smem layout, LDS.64).
template <int CIN, int COUT, int HIN, int OCP, int ICB, int PT>
__global__ void conv_block_p2_kernel(const float* __restrict__ in, const float* __restrict__ w,
                                     const float* __restrict__ cb, const float* __restrict__ gg,
                                     const float* __restrict__ bb, const float* __restrict__ mm,
                                     const float* __restrict__ vv, float* __restrict__ out) {
    constexpr int HOUT = HIN / 2;
    constexpr int TW = HIN + 2;
    constexpr int TDIM = HOUT / PT;
    constexpr int SP = TDIM * TDIM;
    constexpr int NT = OCP * SP;
    constexpr int PS = 2 * PT + 2;

    __shared__ float2 tile2[ICB * TW * TW];   // value duplicated (broadcast pairs)
    __shared__ float2 ws2[OCP * ICB * 9];     // (w[oc_even], w[oc_odd]) pairs

    int b = blockIdx.y;
    int oc0 = blockIdx.x * (2 * OCP);
    int tid = threadIdx.x;
    int pair = tid / SP;
    int sp = tid % SP;
    int th = sp / TDIM, tw = sp % TDIM;
    int rbase = th * 2 * PT;
    int cbase = tw * 2 * PT;

    ull acc[2 * PT][2 * PT];
#pragma unroll
    for (int i = 0; i < 2 * PT; i++)
#pragma unroll
        for (int j = 0; j < 2 * PT; j++) acc[i][j] = 0ULL;

    const float* inb = in + (size_t)b * CIN * HIN * HIN;

    for (int ic0 = 0; ic0 < CIN; ic0 += ICB) {
        // load input tile (zero-padded halo), duplicated for broadcast
        for (int i = tid; i < ICB * TW * TW; i += NT) {
            int ii = i / (TW * TW);
            int rem = i % (TW * TW);
            int r = rem / TW, c = rem % TW;
            float val = 0.f;
            if (r >= 1 && r <= HIN && c >= 1 && c <= HIN)
                val = inb[((size_t)(ic0 + ii) * HIN + (r - 1)) * HIN + (c - 1)];
            tile2[i] = make_float2(val, val);
        }
        // load weight pairs (interleaved)
        for (int i = tid; i < OCP * ICB * 9; i += NT) {
            int pp = i / (ICB * 9);
            int rem = i % (ICB * 9);
            int ii = rem / 9, kk = rem % 9;
            float we = w[((size_t)(oc0 + 2 * pp + 0) * CIN + (ic0 + ii)) * 9 + kk];
            float wo = w[((size_t)(oc0 + 2 * pp + 1) * CIN + (ic0 + ii)) * 9 + kk];
            ws2[i] = make_float2(we, wo);
        }
        __syncthreads();

#pragma unroll 2
        for (int ii = 0; ii < ICB; ii++) {
            const ull* tp = reinterpret_cast<const ull*>(&tile2[ii * TW * TW]);
            ull patch[PS][PS];
#pragma unroll
            for (int i = 0; i < PS; i++)
#pragma unroll
                for (int j = 0; j < PS; j++)
                    patch[i][j] = tp[(rbase + i) * TW + (cbase + j)];
            const ull* wk = reinterpret_cast<const ull*>(&ws2[(pair * ICB + ii) * 9]);
            ull w0 = wk[0], w1 = wk[1], w2 = wk[2], w3 = wk[3], w4 = wk[4],
                w5 = wk[5], w6 = wk[6], w7 = wk[7], w8 = wk[8];
#pragma unroll
            for (int py = 0; py < 2 * PT; py++)
#pragma unroll
                for (int px = 0; px < 2 * PT; px++) {
                    ull s = acc[py][px];
                    s = ffma2(patch[py + 0][px + 0], w0, s);
                    s = ffma2(patch[py + 0][px + 1], w1, s);
                    s = ffma2(patch[py + 0][px + 2], w2, s);
                    s = ffma2(patch[py + 1][px + 0], w3, s);
                    s = ffma2(patch[py + 1][px + 1], w4, s);
                    s = ffma2(patch[py + 1][px + 2], w5, s);
                    s = ffma2(patch[py + 2][px + 0], w6, s);
                    s = ffma2(patch[py + 2][px + 1], w7, s);
                    s = ffma2(patch[py + 2][px + 2], w8, s);
                    acc[py][px] = s;
                }
        }
        __syncthreads();
    }

    // epilogue: BN + ReLU + 2x2 maxpool, for both channels of the pair
    int oce = oc0 + 2 * pair;
    int oco = oce + 1;
    float inv0 = gg[oce] * rsqrtf(vv[oce] + EPS);
    float bi0 = (cb[oce] - mm[oce]) * inv0 + bb[oce];
    float inv1 = gg[oco] * rsqrtf(vv[oco] + EPS);
    float bi1 = (cb[oco] - mm[oco]) * inv1 + bb[oco];

#pragma unroll
    for (int pp = 0; pp < PT; pp++)
#pragma unroll
        for (int qq = 0; qq < PT; qq++) {
            F2U u00, u01, u10, u11;
            u00.u = acc[2 * pp + 0][2 * qq + 0];
            u01.u = acc[2 * pp + 0][2 * qq + 1];
            u10.u = acc[2 * pp + 1][2 * qq + 0];
            u11.u = acc[2 * pp + 1][2 * qq + 1];
            float e00 = fmaxf(fmaf(u00.f.x, inv0, bi0), 0.f);
            float e01 = fmaxf(fmaf(u01.f.x, inv0, bi0), 0.f);
            float e10 = fmaxf(fmaf(u10.f.x, inv0, bi0), 0.f);
            float e11 = fmaxf(fmaf(u11.f.x, inv0, bi0), 0.f);
            float me = fmaxf(fmaxf(e00, e01), fmaxf(e10, e11));
            float o00 = fmaxf(fmaf(u00.f.y, inv1, bi1), 0.f);
            float o01 = fmaxf(fmaf(u01.f.y, inv1, bi1), 0.f);
            float o10 = fmaxf(fmaf(u10.f.y, inv1, bi1), 0.f);
            float o11 = fmaxf(fmaf(u11.f.y, inv1, bi1), 0.f);
            float mo = fmaxf(fmaxf(o00, o01), fmaxf(o10, o11));
            int PH = th * PT + pp, PW = tw * PT + qq;
            out[(((size_t)b * COUT + oce) * HOUT + PH) * HOUT + PW] = me;
            out[(((size_t)b * COUT + oco) * HOUT + PH) * HOUT + PW] = mo;
        }
}

// ---------------- register-tiled linear: C[M,N] = A[M,K] @ W[N,K]^T + bias ----------------
// 64x64 tile, 256 threads (16x16), 4x4 outputs per thread, K step 16.
// Requires M%64==0, N%64==0, K%16==0 (true for all three layers here).
__global__ void linear64_kernel(const float* __restrict__ A, const float* __restrict__ W,
                                const float* __restrict__ bias, float* __restrict__ C,
                                int M, int N, int K) {
    __shared__ float As[16][64];
    __shared__ float Ws[16][64];
    int tx = threadIdx.x & 15;
    int ty = threadIdx.x >> 4;
    int row0 = blockIdx.y * 64;
    int col0 = blockIdx.x * 64;

    float acc[4][4];
#pragma unroll
    for (int i = 0; i < 4; i++)
#pragma unroll
        for (int j = 0; j < 4; j++) acc[i][j] = 0.f;

    // each thread loads one float4 along K per tile: m = tid/4, kq = (tid%4)*4
    int lm = threadIdx.x >> 2;
    int lk = (threadIdx.x & 3) << 2;

    for (int k0 = 0; k0 < K; k0 += 16) {
        float4 av = *reinterpret_cast<const float4*>(&A[(size_t)(row0 + lm) * K + k0 + lk]);
        float4 wv = *reinterpret_cast<const float4*>(&W[(size_t)(col0 + lm) * K + k0 + lk]);
        As[lk + 0][lm] = av.x; As[lk + 1][lm] = av.y; As[lk + 2][lm] = av.z; As[lk + 3][lm] = av.w;
        Ws[lk + 0][lm] = wv.x; Ws[lk + 1][lm] = wv.y; Ws[lk + 2][lm] = wv.z; Ws[lk + 3][lm] = wv.w;
        __syncthreads();
#pragma unroll
        for (int kk = 0; kk < 16; kk++) {
            float ra[4], rb[4];
#pragma unroll
            for (int i = 0; i < 4; i++) ra[i] = As[kk][ty * 4 + i];
#pragma unroll
            for (int j = 0; j < 4; j++) rb[j] = Ws[kk][tx * 4 + j];
#pragma unroll
            for (int i = 0; i < 4; i++)
#pragma unroll
                for (int j = 0; j < 4; j++)
                    acc[i][j] = fmaf(ra[i], rb[j], acc[i][j]);
        }
        __syncthreads();
    }
#pragma unroll
    for (int i = 0; i < 4; i++) {
        int r = row0 + ty * 4 + i;
#pragma unroll
        for (int j = 0; j < 4; j++) {
            int c = col0 + tx * 4 + j;
            C[(size_t)r * N + c] = acc[i][j] + bias[c];
        }
    }
}

// ---------------- attention epilogue ----------------
__global__ void attention_kernel(const float* __restrict__ out3, const float* __restrict__ q,
                                 const float* __restrict__ fc3_w, const float* __restrict__ fc3_b,
                                 float* __restrict__ out) {
    int b = blockIdx.x;
    __shared__ float s3[64 * 36];
    __shared__ float sq[64];
    __shared__ float sc[36];
    __shared__ float sg[64];
    int tid = threadIdx.x;  // 64 threads
    for (int i = tid; i < 64 * 36; i += 64) s3[i] = out3[(size_t)b * 64 * 36 + i];
    sq[tid] = q[(size_t)b * 64 + tid];
    __syncthreads();
    if (tid < 36) {
        float s = 0.f;
#pragma unroll
        for (int c = 0; c < 64; c++) s = fmaf(s3[c * 36 + tid], sq[c], s);
        sc[tid] = s;
    }
    __syncthreads();
    if (tid == 0) {
        float mx = sc[0];
        for (int i = 1; i < 36; i++) mx = fmaxf(mx, sc[i]);
        float sum = 0.f;
        for (int i = 0; i < 36; i++) { float e = expf(sc[i] - mx); sc[i] = e; sum += e; }
        float invs = 1.f / sum;
        for (int i = 0; i < 36; i++) sc[i] *= invs;
    }
    __syncthreads();
    {
        float s = 0.f;
#pragma unroll
        for (int hw = 0; hw < 36; hw++) s = fmaf(s3[tid * 36 + hw], sc[hw], s);
        sg[tid] = s;
    }
    __syncthreads();
    if (tid < 7) {
        float s = fc3_b[tid];
#pragma unroll
        for (int c = 0; c < 64; c++) s = fmaf(sg[c], fc3_w[tid * 64 + c], s);
        out[(size_t)b * 7 + tid] = s;
    }
}

// ---------------- launch ----------------
extern "C" void kernel_launch(void* const* d_in, const int* in_sizes, int n_in,
                              void* d_out, int out_size) {
    const float* x      = (const float*)d_in[0];
    const float* c1w    = (const float*)d_in[1];
    const float* c1b    = (const float*)d_in[2];
    const float* bn1g   = (const float*)d_in[3];
    const float* bn1b   = (const float*)d_in[4];
    const float* bn1m   = (const float*)d_in[5];
    const float* bn1v   = (const float*)d_in[6];
    const float* c2w    = (const float*)d_in[7];
    const float* c2b    = (const float*)d_in[8];
    const float* bn2g   = (const float*)d_in[9];
    const float* bn2b   = (const float*)d_in[10];
    const float* bn2m   = (const float*)d_in[11];
    const float* bn2v   = (const float*)d_in[12];
    const float* c3w    = (const float*)d_in[13];
    const float* c3b    = (const float*)d_in[14];
    const float* bn3g   = (const float*)d_in[15];
    const float* bn3b   = (const float*)d_in[16];
    const float* bn3m   = (const float*)d_in[17];
    const float* bn3v   = (const float*)d_in[18];
    const float* fc1w   = (const float*)d_in[19];
    const float* fc1b   = (const float*)d_in[20];
    const float* fc2w   = (const float*)d_in[21];
    const float* fc2b   = (const float*)d_in[22];
    const float* attw   = (const float*)d_in[23];
    const float* attb   = (const float*)d_in[24];
    const float* fc3w   = (const float*)d_in[25];
    const float* fc3b   = (const float*)d_in[26];
    float* outp = (float*)d_out;

    float *p_out1, *p_out2, *p_out3, *p_fc1, *p_fc2, *p_q;
    cudaGetSymbolAddress((void**)&p_out1, g_out1);
    cudaGetSymbolAddress((void**)&p_out2, g_out2);
    cudaGetSymbolAddress((void**)&p_out3, g_out3);
    cudaGetSymbolAddress((void**)&p_fc1, g_fc1);
    cudaGetSymbolAddress((void**)&p_fc2, g_fc2);
    cudaGetSymbolAddress((void**)&p_q, g_q);

    // block1: [B,1,48,48] -> [B,256,24,24]
    block1_kernel<<<dim3(256 / OCB1, BATCH), 288>>>(x, c1w, c1b, bn1g, bn1b, bn1m, bn1v, p_out1);

    // block2 (packed f32x2): [B,256,24,24] -> [B,128,12,12]
    // OCP=8 pairs (16 oc/block), ICB=4, PT=2 -> 288 threads, grid (8, 512)
    conv_block_p2_kernel<256, 128, 24, 8, 4, 2>
        <<<dim3(128 / 16, BATCH), 8 * 36>>>(p_out1, c2w, c2b, bn2g, bn2b, bn2m, bn2v, p_out2);

    // block3 (packed f32x2): [B,128,12,12] -> [B,64,6,6]
    // OCP=8 pairs (16 oc/block), ICB=8, PT=1 -> 288 threads, grid (4, 512)
    conv_block_p2_kernel<128, 64, 12, 8, 8, 1>
        <<<dim3(64 / 16, BATCH), 8 * 36>>>(p_out2, c3w, c3b, bn3g, bn3b, bn3m, bn3v, p_out3);

    // fc1: [512,2304] -> [512,512]
    linear64_kernel<<<dim3(512 / 64, BATCH / 64), 256>>>(p_out3, fc1w, fc1b, p_fc1, BATCH, 512, 2304);
    // fc2: [512,512] -> [512,256]
    linear64_kernel<<<dim3(256 / 64, BATCH / 64), 256>>>(p_fc1, fc2w, fc2b, p_fc2, BATCH, 256, 512);
    // att: [512,256] -> [512,64]
    linear64_kernel<<<dim3(64 / 64, BATCH / 64), 256>>>(p_fc2, attw, attb, p_q, BATCH, 64, 256);

    // attention + fc3 -> [512,7]
    attention_kernel<<<BATCH, 64>>>(p_out3, p_q, fc3w, fc3b, outp);
}

// round 3
// speedup vs baseline: 5.7537x; 5.7537x over previous
#include <cuda_runtime.h>
#include <cuda_bf16.h>
#include <math.h>

#define BATCH 512
#define EPS 1e-5f

// ---------------- scratch (no allocations allowed) ----------------
__device__ float g_act1[BATCH * 24 * 24 * 256];   // NHWC
__device__ float g_pre2[BATCH * 24 * 24 * 128];   // NHWC (pre-pool)
__device__ float g_act2[BATCH * 12 * 12 * 128];   // NHWC
__device__ float g_pre3[BATCH * 12 * 12 * 64];    // NHWC (pre-pool)
__device__ float g_out3[BATCH * 64 * 36];         // NCHW
__device__ float g_fc1[BATCH * 512];
__device__ float g_fc2[BATCH * 256];
__device__ float g_q[BATCH * 64];
__device__ float g_wt2[9 * 256 * 128];            // [tap][ic][oc], tf32-rounded
__device__ float g_wt3[9 * 128 * 64];

__device__ __forceinline__ unsigned f2tf(float f) {
    unsigned u;
    asm("cvt.rna.tf32.f32 %0, %1;" : "=r"(u) : "f"(f));
    return u;
}

// ---------------- weight transform: [O][I][9] -> [tap][ic][oc] (tf32-rounded) ----------------
__global__ void wtrans_kernel(const float* __restrict__ w, float* __restrict__ wt,
                              int CIN, int COUT) {
    int n = 9 * CIN * COUT;
    for (int idx = blockIdx.x * blockDim.x + threadIdx.x; idx < n; idx += gridDim.x * blockDim.x) {
        int t = idx / (CIN * COUT);
        int ic = (idx / COUT) % CIN;
        int oc = idx % COUT;
        float v = w[((size_t)oc * CIN + ic) * 9 + t];
        wt[idx] = __uint_as_float(f2tf(v));
    }
}

// ---------------- block1: conv(1->256,48x48)+BN+ReLU+pool -> NHWC [B,24,24,256] ----------------
#define OCB1 32
__global__ void block1_kernel(const float* __restrict__ x, const float* __restrict__ w,
                              const float* __restrict__ cb, const float* __restrict__ gg,
                              const float* __restrict__ bb, const float* __restrict__ mm,
                              const float* __restrict__ vv, float* __restrict__ out) {
    int b = blockIdx.y;
    int oc0 = blockIdx.x * OCB1;
    __shared__ float tile[50 * 50];
    __shared__ float ws[OCB1 * 9];
    __shared__ float sa[OCB1], sc[OCB1];
    int tid = threadIdx.x;

    const float* xb = x + (size_t)b * 48 * 48;
    for (int i = tid; i < 2500; i += blockDim.x) {
        int r = i / 50, c = i % 50;
        float val = 0.f;
        if (r >= 1 && r <= 48 && c >= 1 && c <= 48) val = xb[(r - 1) * 48 + (c - 1)];
        tile[i] = val;
    }
    for (int i = tid; i < OCB1 * 9; i += blockDim.x) ws[i] = w[oc0 * 9 + i];
    if (tid < OCB1) {
        int oc = oc0 + tid;
        float inv = gg[oc] * rsqrtf(vv[oc] + EPS);
        sa[tid] = inv;
        sc[tid] = (cb[oc] - mm[oc]) * inv + bb[oc];
    }
    __syncthreads();

    for (int it = tid; it < 576; it += blockDim.x) {
        int ph = it / 24, pw = it % 24;
        float p[4][4];
#pragma unroll
        for (int i = 0; i < 4; i++)
#pragma unroll
            for (int j = 0; j < 4; j++)
                p[i][j] = tile[(2 * ph + i) * 50 + (2 * pw + j)];
        float* ob = &out[(((size_t)b * 24 + ph) * 24 + pw) * 256 + oc0];
#pragma unroll 4
        for (int oo = 0; oo < OCB1; oo++) {
            float a = sa[oo], cc = sc[oo];
            const float* wk = &ws[oo * 9];
            float w0 = wk[0], w1 = wk[1], w2 = wk[2], w3 = wk[3], w4 = wk[4],
                  w5 = wk[5], w6 = wk[6], w7 = wk[7], w8 = wk[8];
            float mx = -INFINITY;
#pragma unroll
            for (int py = 0; py < 2; py++)
#pragma unroll
                for (int px = 0; px < 2; px++) {
                    float s = p[py + 0][px + 0] * w0 + p[py + 0][px + 1] * w1 + p[py + 0][px + 2] * w2
                            + p[py + 1][px + 0] * w3 + p[py + 1][px + 1] * w4 + p[py + 1][px + 2] * w5
                            + p[py + 2][px + 0] * w6 + p[py + 2][px + 1] * w7 + p[py + 2][px + 2] * w8;
                    float y = fmaxf(fmaf(s, a, cc), 0.f);
                    mx = fmaxf(mx, y);
                }
            ob[oo] = mx;
        }
    }
}

// ---------------- tensor-core implicit-GEMM conv (3x3, pad 1) + BN + ReLU, NHWC ----------------
// 9-tap shifted GEMM over ic chunks of 32. tf32 mma.sync m16n8k8, fp32 accumulate.
// Each warp: 48 spatial positions (RPW rows x WIDTH cols) x NPW output channels.
template <int CIN, int COUT, int WIDTH, int SLAB, int RPW, int WM, int WN, int APITCH, int WPITCH>
__global__ void __launch_bounds__(WM * WN * 32, 1)
conv_tc_kernel(const float* __restrict__ act, const float* __restrict__ wt,
               const float* __restrict__ cb, const float* __restrict__ gg,
               const float* __restrict__ bb, const float* __restrict__ mm,
               const float* __restrict__ vv, float* __restrict__ pre) {
    constexpr int ICB = 32;
    constexpr int HC = WIDTH + 2;
    constexpr int NPOS = (SLAB + 2) * HC;
    constexpr int NT = WM * WN * 32;
    constexpr int NPW = COUT / WN;
    constexpr int NT2 = NPW / 8;
    constexpr int MT = 3;
    constexpr int NCH = CIN / ICB;
    constexpr int ITERS = NCH * 9;
    constexpr int QW = ICB * COUT / 4;
    constexpr int PFQ = (QW + NT - 1) / NT;

    extern __shared__ float smem[];
    unsigned* atile = (unsigned*)smem;                       // [32][APITCH] tf32 bits
    unsigned* wsm = (unsigned*)(smem + 32 * APITCH);         // [2][32][WPITCH]
    float* sInv = smem + 32 * APITCH + 2 * 32 * WPITCH;
    float* sBias = sInv + COUT;

    int b = blockIdx.y;
    int r0 = blockIdx.x * SLAB;
    int tid = threadIdx.x;
    int warp = tid >> 5, lane = tid & 31;
    int g = lane >> 2, tig = lane & 3;
    int warpM = warp / WN, warpN = warp % WN;

    if (tid < COUT) {
        float inv = gg[tid] * rsqrtf(vv[tid] + EPS);
        sInv[tid] = inv;
        sBias[tid] = (cb[tid] - mm[tid]) * inv + bb[tid];
    }

    const float* actb = act + (size_t)b * WIDTH * WIDTH * CIN;

    float acc[MT][NT2][4];
#pragma unroll
    for (int mt = 0; mt < MT; mt++)
#pragma unroll
        for (int nt = 0; nt < NT2; nt++)
#pragma unroll
            for (int i = 0; i < 4; i++) acc[mt][nt][i] = 0.f;

    float4 pref[PFQ];

    // ---- A tile loader (activations, zero-padded halo, tf32-rounded) ----
    auto load_atile = [&](int ic0) {
        for (int i = tid; i < NPOS * (ICB / 4); i += NT) {
            int pos = i >> 3, kq = i & 7;          // ICB/4 == 8
            int tr = pos / HC, tc = pos % HC;
            int ir = r0 - 1 + tr, icl = tc - 1;
            float4 v = make_float4(0.f, 0.f, 0.f, 0.f);
            if (ir >= 0 && ir < WIDTH && icl >= 0 && icl < WIDTH)
                v = *(const float4*)&actb[((size_t)ir * WIDTH + icl) * CIN + ic0 + kq * 4];
            int k = kq * 4;
            atile[(k + 0) * APITCH + pos] = f2tf(v.x);
            atile[(k + 1) * APITCH + pos] = f2tf(v.y);
            atile[(k + 2) * APITCH + pos] = f2tf(v.z);
            atile[(k + 3) * APITCH + pos] = f2tf(v.w);
        }
    };
    // ---- weight prefetch to regs / store to smem buffer ----
    auto lw = [&](int it) {
        const float* base = wt + ((size_t)(it % 9) * CIN + (it / 9) * ICB) * COUT;
#pragma unroll
        for (int q = 0; q < PFQ; q++) {
            int idx = tid + q * NT;
            if (idx < QW) pref[q] = *(const float4*)&base[idx * 4];
        }
    };
    auto sw = [&](int buf) {
        unsigned* wb = wsm + buf * 32 * WPITCH;
#pragma unroll
        for (int q = 0; q < PFQ; q++) {
            int idx = tid + q * NT;
            if (idx < QW) {
                int k = idx / (COUT / 4), nq = idx % (COUT / 4);
                uint4 u;
                u.x = __float_as_uint(pref[q].x);
                u.y = __float_as_uint(pref[q].y);
                u.z = __float_as_uint(pref[q].z);
                u.w = __float_as_uint(pref[q].w);
                *(uint4*)&wb[k * WPITCH + nq * 4] = u;
            }
        }
    };

    load_atile(0);
    lw(0);
    sw(0);
    __syncthreads();

    for (int it = 0; it < ITERS; ++it) {
        int buf = it & 1;
        if (it + 1 < ITERS) lw(it + 1);

        int tap = it % 9;
        int dy = tap / 3, dx = tap % 3;
        int pl[MT], ph[MT];
#pragma unroll
        for (int mt = 0; mt < MT; mt++) {
            int m = mt * 16 + g;
            pl[mt] = (warpM * RPW + m / WIDTH + dy) * HC + m % WIDTH + dx;
            m += 8;
            ph[mt] = (warpM * RPW + m / WIDTH + dy) * HC + m % WIDTH + dx;
        }
        const unsigned* wb = wsm + buf * 32 * WPITCH;
#pragma unroll
        for (int ks = 0; ks < 4; ks++) {
            unsigned af[MT][4];
            int k = ks * 8 + tig;
#pragma unroll
            for (int mt = 0; mt < MT; mt++) {
                af[mt][0] = atile[k * APITCH + pl[mt]];
                af[mt][1] = atile[k * APITCH + ph[mt]];
                af[mt][2] = atile[(k + 4) * APITCH + pl[mt]];
                af[mt][3] = atile[(k + 4) * APITCH + ph[mt]];
            }
#pragma unroll
            for (int nt = 0; nt < NT2; nt++) {
                unsigned b0 = wb[k * WPITCH + warpN * NPW + nt * 8 + g];
                unsigned b1 = wb[(k + 4) * WPITCH + warpN * NPW + nt * 8 + g];
#pragma unroll
                for (int mt = 0; mt < MT; mt++) {
                    asm volatile(
                        "mma.sync.aligned.m16n8k8.row.col.f32.tf32.tf32.f32 "
                        "{%0,%1,%2,%3}, {%4,%5,%6,%7}, {%8,%9}, {%0,%1,%2,%3};"
                        : "+f"(acc[mt][nt][0]), "+f"(acc[mt][nt][1]),
                          "+f"(acc[mt][nt][2]), "+f"(acc[mt][nt][3])
                        : "r"(af[mt][0]), "r"(af[mt][1]), "r"(af[mt][2]), "r"(af[mt][3]),
                          "r"(b0), "r"(b1));
                }
            }
        }
        if (it + 1 < ITERS) {
            if ((it + 1) % 9 == 0) {
                __syncthreads();
                load_atile(((it + 1) / 9) * ICB);
            }
            sw(buf ^ 1);
        }
        __syncthreads();
    }

    // epilogue: BN + ReLU, write pre-pool NHWC
    float* preb = pre + (size_t)b * WIDTH * WIDTH * COUT;
#pragma unroll
    for (int mt = 0; mt < MT; mt++) {
        int m = mt * 16 + g;
        int row = r0 + warpM * RPW + m / WIDTH, col = m % WIDTH;
        int m2 = m + 8;
        int row2 = r0 + warpM * RPW + m2 / WIDTH, col2 = m2 % WIDTH;
#pragma unroll
        for (int nt = 0; nt < NT2; nt++) {
            int oc = warpN * NPW + nt * 8 + tig * 2;
            float inv0 = sInv[oc], bi0 = sBias[oc];
            float inv1 = sInv[oc + 1], bi1 = sBias[oc + 1];
            float2 v;
            v.x = fmaxf(fmaf(acc[mt][nt][0], inv0, bi0), 0.f);
            v.y = fmaxf(fmaf(acc[mt][nt][1], inv1, bi1), 0.f);
            *(float2*)&preb[((size_t)row * WIDTH + col) * COUT + oc] = v;
            v.x = fmaxf(fmaf(acc[mt][nt][2], inv0, bi0), 0.f);
            v.y = fmaxf(fmaf(acc[mt][nt][3], inv1, bi1), 0.f);
            *(float2*)&preb[((size_t)row2 * WIDTH + col2) * COUT + oc] = v;
        }
    }
}

// ---------------- 2x2 max pools ----------------
__global__ void pool2_kernel(const float* __restrict__ pre, float* __restrict__ out) {
    // [B,24,24,128] -> [B,12,12,128] NHWC
    int idx = blockIdx.x * blockDim.x + threadIdx.x;
    if (idx >= BATCH * 12 * 12 * 128) return;
    int oc = idx & 127;
    int rest = idx >> 7;
    int pc = rest % 12;
    int pr = (rest / 12) % 12;
    int b = rest / 144;
    const float* p = pre + (((size_t)b * 24 + 2 * pr) * 24 + 2 * pc) * 128 + oc;
    out[idx] = fmaxf(fmaxf(p[0], p[128]), fmaxf(p[24 * 128], p[24 * 128 + 128]));
}

__global__ void pool3_kernel(const float* __restrict__ pre, float* __restrict__ out) {
    // [B,12,12,64] NHWC -> [B,64,6,6] NCHW
    int idx = blockIdx.x * blockDim.x + threadIdx.x;
    if (idx >= BATCH * 64 * 36) return;
    int pw = idx % 6;
    int ph = (idx / 6) % 6;
    int c = (idx / 36) % 64;
    int b = idx / (36 * 64);
    const float* p = pre + (((size_t)b * 12 + 2 * ph) * 12 + 2 * pw) * 64 + c;
    out[idx] = fmaxf(fmaxf(p[0], p[64]), fmaxf(p[12 * 64], p[12 * 64 + 64]));
}

// ---------------- linear: C[M,N] = A[M,K] @ W[N,K]^T + bias (16x16 tiles) ----------------
__global__ void linear_kernel(const float* __restrict__ A, const float* __restrict__ W,
                              const float* __restrict__ bias, float* __restrict__ C,
                              int M, int N, int K) {
    __shared__ float As[16][16];
    __shared__ float Ws[16][17];
    int row = blockIdx.y * 16 + threadIdx.y;
    int col = blockIdx.x * 16 + threadIdx.x;
    float acc = 0.f;
    for (int k0 = 0; k0 < K; k0 += 16) {
        int ka = k0 + threadIdx.x;
        As[threadIdx.y][threadIdx.x] = (row < M && ka < K) ? A[(size_t)row * K + ka] : 0.f;
        int wr = blockIdx.x * 16 + threadIdx.y;
        Ws[threadIdx.y][threadIdx.x] = (wr < N && ka < K) ? W[(size_t)wr * K + ka] : 0.f;
        __syncthreads();
#pragma unroll
        for (int kk = 0; kk < 16; kk++)
            acc = fmaf(As[threadIdx.y][kk], Ws[threadIdx.x][kk], acc);
        __syncthreads();
    }
    if (row < M && col < N) C[(size_t)row * N + col] = acc + bias[col];
}

// ---------------- attention epilogue ----------------
__global__ void attention_kernel(const float* __restrict__ out3, const float* __restrict__ q,
                                 const float* __restrict__ fc3_w, const float* __restrict__ fc3_b,
                                 float* __restrict__ out) {
    int b = blockIdx.x;
    __shared__ float s3[64 * 36];
    __shared__ float sq[64];
    __shared__ float sc[36];
    __shared__ float sg[64];
    int tid = threadIdx.x;  // 64 threads
    for (int i = tid; i < 64 * 36; i += 64) s3[i] = out3[(size_t)b * 64 * 36 + i];
    sq[tid] = q[(size_t)b * 64 + tid];
    __syncthreads();
    if (tid < 36) {
        float s = 0.f;
#pragma unroll
        for (int c = 0; c < 64; c++) s = fmaf(s3[c * 36 + tid], sq[c], s);
        sc[tid] = s;
    }
    __syncthreads();
    if (tid == 0) {
        float mx = sc[0];
        for (int i = 1; i < 36; i++) mx = fmaxf(mx, sc[i]);
        float sum = 0.f;
        for (int i = 0; i < 36; i++) { float e = expf(sc[i] - mx); sc[i] = e; sum += e; }
        float invs = 1.f / sum;
        for (int i = 0; i < 36; i++) sc[i] *= invs;
    }
    __syncthreads();
    {
        float s = 0.f;
#pragma unroll
        for (int hw = 0; hw < 36; hw++) s = fmaf(s3[tid * 36 + hw], sc[hw], s);
        sg[tid] = s;
    }
    __syncthreads();
    if (tid < 7) {
        float s = fc3_b[tid];
#pragma unroll
        for (int c = 0; c < 64; c++) s = fmaf(sg[c], fc3_w[tid * 64 + c], s);
        out[(size_t)b * 7 + tid] = s;
    }
}

// ---------------- launch ----------------
extern "C" void kernel_launch(void* const* d_in, const int* in_sizes, int n_in,
                              void* d_out, int out_size) {
    const float* x    = (const float*)d_in[0];
    const float* c1w  = (const float*)d_in[1];
    const float* c1b  = (const float*)d_in[2];
    const float* bn1g = (const float*)d_in[3];
    const float* bn1b = (const float*)d_in[4];
    const float* bn1m = (const float*)d_in[5];
    const float* bn1v = (const float*)d_in[6];
    const float* c2w  = (const float*)d_in[7];
    const float* c2b  = (const float*)d_in[8];
    const float* bn2g = (const float*)d_in[9];
    const float* bn2b = (const float*)d_in[10];
    const float* bn2m = (const float*)d_in[11];
    const float* bn2v = (const float*)d_in[12];
    const float* c3w  = (const float*)d_in[13];
    const float* c3b  = (const float*)d_in[14];
    const float* bn3g = (const float*)d_in[15];
    const float* bn3b = (const float*)d_in[16];
    const float* bn3m = (const float*)d_in[17];
    const float* bn3v = (const float*)d_in[18];
    const float* fc1w = (const float*)d_in[19];
    const float* fc1b = (const float*)d_in[20];
    const float* fc2w = (const float*)d_in[21];
    const float* fc2b = (const float*)d_in[22];
    const float* attw = (const float*)d_in[23];
    const float* attb = (const float*)d_in[24];
    const float* fc3w = (const float*)d_in[25];
    const float* fc3b = (const float*)d_in[26];
    float* outp = (float*)d_out;

    float *p_act1, *p_pre2, *p_act2, *p_pre3, *p_out3, *p_fc1, *p_fc2, *p_q, *p_wt2, *p_wt3;
    cudaGetSymbolAddress((void**)&p_act1, g_act1);
    cudaGetSymbolAddress((void**)&p_pre2, g_pre2);
    cudaGetSymbolAddress((void**)&p_act2, g_act2);
    cudaGetSymbolAddress((void**)&p_pre3, g_pre3);
    cudaGetSymbolAddress((void**)&p_out3, g_out3);
    cudaGetSymbolAddress((void**)&p_fc1, g_fc1);
    cudaGetSymbolAddress((void**)&p_fc2, g_fc2);
    cudaGetSymbolAddress((void**)&p_q, g_q);
    cudaGetSymbolAddress((void**)&p_wt2, g_wt2);
    cudaGetSymbolAddress((void**)&p_wt3, g_wt3);

    const int SMEM2 = (32 * 261 + 2 * 32 * 136 + 2 * 128) * 4;  // 69248 B
    const int SMEM3 = (32 * 197 + 2 * 32 * 72 + 2 * 64) * 4;    // 44160 B
    cudaFuncSetAttribute((const void*)conv_tc_kernel<256, 128, 24, 8, 2, 4, 2, 261, 136>,
                         cudaFuncAttributeMaxDynamicSharedMemorySize, SMEM2);
    cudaFuncSetAttribute((const void*)conv_tc_kernel<128, 64, 12, 12, 4, 3, 2, 197, 72>,
                         cudaFuncAttributeMaxDynamicSharedMemorySize, SMEM3);

    // weight transforms (tiny)
    wtrans_kernel<<<288, 256>>>(c2w, p_wt2, 256, 128);
    wtrans_kernel<<<72, 256>>>(c3w, p_wt3, 128, 64);

    // block1 -> NHWC act1
    block1_kernel<<<dim3(256 / OCB1, BATCH), 288>>>(x, c1w, c1b, bn1g, bn1b, bn1m, bn1v, p_act1);

    // conv2 (tensor core) -> pre2, pool -> act2
    conv_tc_kernel<256, 128, 24, 8, 2, 4, 2, 261, 136>
        <<<dim3(3, BATCH), 256, SMEM2>>>(p_act1, p_wt2, c2b, bn2g, bn2b, bn2m, bn2v, p_pre2);
    pool2_kernel<<<(BATCH * 12 * 12 * 128 + 255) / 256, 256>>>(p_pre2, p_act2);

    // conv3 (tensor core) -> pre3, pool -> out3 (NCHW)
    conv_tc_kernel<128, 64, 12, 12, 4, 3, 2, 197, 72>
        <<<dim3(1, BATCH), 192, SMEM3>>>(p_act2, p_wt3, c3b, bn3g, bn3b, bn3m, bn3v, p_pre3);
    pool3_kernel<<<(BATCH * 64 * 36 + 255) / 256, 256>>>(p_pre3, p_out3);

    // FCs
    linear_kernel<<<dim3(512 / 16, BATCH / 16), dim3(16, 16)>>>(p_out3, fc1w, fc1b, p_fc1, BATCH, 512, 2304);
    linear_kernel<<<dim3(256 / 16, BATCH / 16), dim3(16, 16)>>>(p_fc1, fc2w, fc2b, p_fc2, BATCH, 256, 512);
    linear_kernel<<<dim3(64 / 16, BATCH / 16), dim3(16, 16)>>>(p_fc2, attw, attb, p_q, BATCH, 64, 256);

    // attention + fc3
    attention_kernel<<<BATCH, 64>>>(p_out3, p_q, fc3w, fc3b, outp);
}